// round 1
// baseline (speedup 1.0000x reference)
#include <cuda_runtime.h>
#include <stdint.h>

// ---------------------------------------------------------------------------
// MagnitudePruning: s = t*magnitude + |x|  (monotone surrogate for mag),
// 2-level radix select (12-bit top / 20-bit low) for the rank-k key,
// then out = (key(s) >= thr_key) ? x : 0.
// ---------------------------------------------------------------------------

#define HIST1_SIZE 4096u          // top 12 bits
#define HIST2_SIZE (1u << 20)     // low 20 bits
#define NBLOCKS 1184              // 8 * 148 SMs
#define NTHREADS 256

__device__ unsigned int g_hist1[HIST1_SIZE];
__device__ unsigned int g_hist2[HIST2_SIZE];
__device__ unsigned int g_partial[1024];
__device__ unsigned int g_b1;
__device__ unsigned int g_r1;       // 1-based remaining rank within bin b1
__device__ unsigned int g_thr_key;

__device__ __forceinline__ unsigned int key_of(float x, float m, float tf) {
    // s = t*m + |x|, explicit non-fused rounding so all passes agree bit-exactly
    float s = __fadd_rn(__fmul_rn(tf, m), fabsf(x));
    return __float_as_uint(s);   // s >= 0 -> bits are order-preserving
}

__device__ __forceinline__ float read_tf(const int* t_ptr) {
    return t_ptr ? (float)(*t_ptr) : 1.0f;
}

// ---------------------------------------------------------------------------
__global__ void zero_kernel() {
    unsigned total = HIST2_SIZE + HIST1_SIZE;
    unsigned stride = gridDim.x * blockDim.x;
    for (unsigned i = blockIdx.x * blockDim.x + threadIdx.x; i < total; i += stride) {
        if (i < HIST2_SIZE) g_hist2[i] = 0u;
        else                g_hist1[i - HIST2_SIZE] = 0u;
    }
}

// ---------------------------------------------------------------------------
__device__ __forceinline__ void agg_shared_add(unsigned* hist, unsigned bin) {
    unsigned act   = __activemask();
    unsigned peers = __match_any_sync(act, bin);
    int      leader = __ffs(peers) - 1;
    if ((int)(threadIdx.x & 31) == leader)
        atomicAdd(&hist[bin], (unsigned)__popc(peers));
}

__global__ void hist1_kernel(const float* __restrict__ xs,
                             const float* __restrict__ ms,
                             const int* __restrict__ t_ptr,
                             unsigned n) {
    __shared__ unsigned sh[HIST1_SIZE];
    for (unsigned i = threadIdx.x; i < HIST1_SIZE; i += blockDim.x) sh[i] = 0u;
    __syncthreads();

    float tf = read_tf(t_ptr);
    unsigned n4 = n >> 2;
    const float4* x4 = (const float4*)xs;
    const float4* m4 = (const float4*)ms;
    unsigned stride = gridDim.x * blockDim.x;
    for (unsigned i = blockIdx.x * blockDim.x + threadIdx.x; i < n4; i += stride) {
        float4 xv = x4[i];
        float4 mv = m4[i];
        agg_shared_add(sh, key_of(xv.x, mv.x, tf) >> 20);
        agg_shared_add(sh, key_of(xv.y, mv.y, tf) >> 20);
        agg_shared_add(sh, key_of(xv.z, mv.z, tf) >> 20);
        agg_shared_add(sh, key_of(xv.w, mv.w, tf) >> 20);
    }
    // scalar tail
    if (blockIdx.x == 0 && threadIdx.x == 0) {
        for (unsigned i = n4 << 2; i < n; i++)
            atomicAdd(&g_hist1[key_of(xs[i], ms[i], tf) >> 20], 1u);
    }
    __syncthreads();
    for (unsigned i = threadIdx.x; i < HIST1_SIZE; i += blockDim.x) {
        unsigned c = sh[i];
        if (c) atomicAdd(&g_hist1[i], c);
    }
}

// ---------------------------------------------------------------------------
// 1 block, 1024 threads. Computes rank R from sparsity and scans the 4096-bin
// histogram to find bin b1 and the remaining rank r1 (1-based).
__global__ void select1_kernel(const float* __restrict__ sparsity, unsigned n) {
    __shared__ unsigned s[1024];
    int t = threadIdx.x;

    unsigned c0 = g_hist1[t * 4 + 0];
    unsigned c1 = g_hist1[t * 4 + 1];
    unsigned c2 = g_hist1[t * 4 + 2];
    unsigned c3 = g_hist1[t * 4 + 3];
    unsigned local = c0 + c1 + c2 + c3;

    s[t] = local;
    __syncthreads();
    for (int off = 1; off < 1024; off <<= 1) {
        unsigned v = (t >= off) ? s[t - off] : 0u;
        __syncthreads();
        s[t] += v;
        __syncthreads();
    }

    // R = idx+1, idx = clip((int)floor(sparsity*n - 1), 0, n-1)  (fp32 math, like jnp)
    float sp   = sparsity[0];
    float fidx = floorf(__fsub_rn(__fmul_rn(sp, (float)n), 1.0f));
    long long idx = (long long)fidx;
    if (idx < 0) idx = 0;
    if (idx > (long long)(n - 1)) idx = (long long)(n - 1);
    unsigned R = (unsigned)idx + 1u;

    unsigned incl   = s[t];
    unsigned before = incl - local;
    if (R > before && R <= incl) {
        unsigned run = before;
        unsigned c[4] = {c0, c1, c2, c3};
        #pragma unroll
        for (int j = 0; j < 4; j++) {
            if (R <= run + c[j]) {
                g_b1 = (unsigned)(t * 4 + j);
                g_r1 = R - run;
                break;
            }
            run += c[j];
        }
    }
}

// ---------------------------------------------------------------------------
__device__ __forceinline__ void hist2_add(unsigned key, unsigned b1) {
    unsigned act  = __activemask();
    bool     pass = (key >> 20) == b1;
    unsigned pm   = __ballot_sync(act, pass);
    if (pass) {
        unsigned low    = key & 0xFFFFFu;
        unsigned peers  = __match_any_sync(pm, low);
        int      leader = __ffs(peers) - 1;
        if ((int)(threadIdx.x & 31) == leader)
            atomicAdd(&g_hist2[low], (unsigned)__popc(peers));
    }
}

__global__ void hist2_kernel(const float* __restrict__ xs,
                             const float* __restrict__ ms,
                             const int* __restrict__ t_ptr,
                             unsigned n) {
    float tf = read_tf(t_ptr);
    unsigned b1 = g_b1;
    unsigned n4 = n >> 2;
    const float4* x4 = (const float4*)xs;
    const float4* m4 = (const float4*)ms;
    unsigned stride = gridDim.x * blockDim.x;
    for (unsigned i = blockIdx.x * blockDim.x + threadIdx.x; i < n4; i += stride) {
        float4 xv = x4[i];
        float4 mv = m4[i];
        hist2_add(key_of(xv.x, mv.x, tf), b1);
        hist2_add(key_of(xv.y, mv.y, tf), b1);
        hist2_add(key_of(xv.z, mv.z, tf), b1);
        hist2_add(key_of(xv.w, mv.w, tf), b1);
    }
    if (blockIdx.x == 0 && threadIdx.x == 0) {
        for (unsigned i = n4 << 2; i < n; i++) {
            unsigned k = key_of(xs[i], ms[i], tf);
            if ((k >> 20) == b1) atomicAdd(&g_hist2[k & 0xFFFFFu], 1u);
        }
    }
}

// ---------------------------------------------------------------------------
// 1024 blocks x 256 threads: chunk sums of the 1M-bin histogram.
__global__ void partial2_kernel() {
    __shared__ unsigned red[256];
    unsigned base = blockIdx.x * 1024u;
    unsigned sum = 0;
    for (unsigned i = threadIdx.x; i < 1024u; i += 256u) sum += g_hist2[base + i];
    red[threadIdx.x] = sum;
    __syncthreads();
    for (int off = 128; off > 0; off >>= 1) {
        if ((int)threadIdx.x < off) red[threadIdx.x] += red[threadIdx.x + off];
        __syncthreads();
    }
    if (threadIdx.x == 0) g_partial[blockIdx.x] = red[0];
}

// 1 block, 1024 threads: scan partials -> chunk, then scan chunk -> exact key.
__global__ void select2_kernel() {
    __shared__ unsigned s[1024];
    __shared__ unsigned s_chunk, s_rank;
    int t = threadIdx.x;
    unsigned R = g_r1;

    unsigned local = g_partial[t];
    s[t] = local;
    __syncthreads();
    for (int off = 1; off < 1024; off <<= 1) {
        unsigned v = (t >= off) ? s[t - off] : 0u;
        __syncthreads();
        s[t] += v;
        __syncthreads();
    }
    unsigned incl   = s[t];
    unsigned before = incl - local;
    if (R > before && R <= incl) { s_chunk = (unsigned)t; s_rank = R - before; }
    __syncthreads();

    unsigned chunk = s_chunk;
    unsigned r2    = s_rank;

    unsigned local2 = g_hist2[chunk * 1024u + t];
    __syncthreads();
    s[t] = local2;
    __syncthreads();
    for (int off = 1; off < 1024; off <<= 1) {
        unsigned v = (t >= off) ? s[t - off] : 0u;
        __syncthreads();
        s[t] += v;
        __syncthreads();
    }
    unsigned incl2   = s[t];
    unsigned before2 = incl2 - local2;
    if (r2 > before2 && r2 <= incl2) {
        g_thr_key = (g_b1 << 20) | (chunk * 1024u + (unsigned)t);
    }
}

// ---------------------------------------------------------------------------
__global__ void apply_kernel(const float* __restrict__ xs,
                             const float* __restrict__ ms,
                             const int* __restrict__ t_ptr,
                             float* __restrict__ out,
                             unsigned n) {
    float tf = read_tf(t_ptr);
    unsigned thr = g_thr_key;
    unsigned n4 = n >> 2;
    const float4* x4 = (const float4*)xs;
    const float4* m4 = (const float4*)ms;
    float4* o4 = (float4*)out;
    unsigned stride = gridDim.x * blockDim.x;
    for (unsigned i = blockIdx.x * blockDim.x + threadIdx.x; i < n4; i += stride) {
        float4 xv = x4[i];
        float4 mv = m4[i];
        float4 ov;
        ov.x = (key_of(xv.x, mv.x, tf) >= thr) ? xv.x : 0.0f;
        ov.y = (key_of(xv.y, mv.y, tf) >= thr) ? xv.y : 0.0f;
        ov.z = (key_of(xv.z, mv.z, tf) >= thr) ? xv.z : 0.0f;
        ov.w = (key_of(xv.w, mv.w, tf) >= thr) ? xv.w : 0.0f;
        o4[i] = ov;
    }
    if (blockIdx.x == 0 && threadIdx.x == 0) {
        for (unsigned i = n4 << 2; i < n; i++)
            out[i] = (key_of(xs[i], ms[i], tf) >= thr) ? xs[i] : 0.0f;
    }
}

// ---------------------------------------------------------------------------
extern "C" void kernel_launch(void* const* d_in, const int* in_sizes, int n_in,
                              void* d_out, int out_size) {
    const float* xs = (const float*)d_in[0];
    const float* ms = (const float*)d_in[1];
    const float* sp = (const float*)d_in[2];
    // d_in[3] = mask (unused by the reference computation)
    const int* t_ptr = (n_in >= 5) ? (const int*)d_in[4] : nullptr;

    unsigned n = (unsigned)in_sizes[0];
    float* out = (float*)d_out;

    zero_kernel<<<512, 256>>>();
    hist1_kernel<<<NBLOCKS, NTHREADS>>>(xs, ms, t_ptr, n);
    select1_kernel<<<1, 1024>>>(sp, n);
    hist2_kernel<<<NBLOCKS, NTHREADS>>>(xs, ms, t_ptr, n);
    partial2_kernel<<<1024, 256>>>();
    select2_kernel<<<1, 1024>>>();
    apply_kernel<<<NBLOCKS, NTHREADS>>>(xs, ms, t_ptr, out, n);
}